// round 14
// baseline (speedup 1.0000x reference)
#include <cuda_runtime.h>
#include <cuda_bf16.h>
#include <cstddef>
#include <cstdint>

#define N_PTS   20000
#define E_EDGES 320000
#define KNN     16
#define FEAT    64
#define R_REP   4

// ---------------- scratch (static device globals; allocation-free) ----------
__device__ float g_x1[(size_t)N_PTS * FEAT];   // 5.12 MB
__device__ float g_sq[20224];                  // padded for tile reads
__device__ int   g_nbr[(size_t)N_PTS * KNN];   // 1.28 MB
__device__ float g_x2[(size_t)N_PTS * FEAT];   // 5.12 MB

// ---------------- helpers ---------------------------------------------------
__device__ __forceinline__ unsigned enc_f(float f) {
    unsigned u = __float_as_uint(f);
    return (u & 0x80000000u) ? ~u : (u | 0x80000000u);
}
__device__ __forceinline__ uint32_t smem_u32(const void* p) {
    uint32_t a;
    asm("{ .reg .u64 t; cvta.to.shared.u64 t, %1; cvt.u32.u64 %0, t; }"
        : "=r"(a) : "l"(p));
    return a;
}
__device__ __forceinline__ unsigned long long ffma2(
    unsigned long long a, unsigned long long b, unsigned long long c) {
    unsigned long long d;
    asm("fma.rn.f32x2 %0, %1, %2, %3;" : "=l"(d) : "l"(a), "l"(b), "l"(c));
    return d;
}
__device__ __forceinline__ float f32x2_sum(unsigned long long v) {
    unsigned lo, hi;
    asm("mov.b64 {%0,%1}, %2;" : "=r"(lo), "=r"(hi) : "l"(v));
    return __uint_as_float(lo) + __uint_as_float(hi);
}
__device__ __forceinline__ void cpa8(uint32_t dst, const void* src) {
    asm volatile("cp.async.ca.shared.global [%0], [%1], 8;"
        :: "r"(dst), "l"(src));
}
__device__ __forceinline__ void cpa16(uint32_t dst, const void* src) {
    asm volatile("cp.async.cg.shared.global [%0], [%1], 16;"
        :: "r"(dst), "l"(src));
}
__device__ __forceinline__ void cpa_commit() {
    asm volatile("cp.async.commit_group;");
}
__device__ __forceinline__ void cpa_wait0() {
    asm volatile("cp.async.wait_group 0;");
}

// ---------------- zero x1 ----------------------------------------------------
__global__ void k_zero_x1() {
    int i = blockIdx.x * blockDim.x + threadIdx.x;
    if (i < N_PTS * FEAT) g_x1[i] = 0.f;
}

// ---------------- stage 1: edge MLP (6->64->64, ReLU) + segment_max ---------
__global__ void __launch_bounds__(256) k_edge(
    const float* __restrict__ pts, const int* __restrict__ ei,
    const float* __restrict__ W1a, const float* __restrict__ b1a,
    const float* __restrict__ W1b, const float* __restrict__ b1b)
{
    __shared__ float sW1a[6 * 64];
    __shared__ float sW1b[64 * 64];
    __shared__ float sh1[64][66];
    int t = threadIdx.x;
    for (int i = t; i < 6 * 64 / 4; i += 256)
        ((float4*)sW1a)[i] = ((const float4*)W1a)[i];
    for (int i = t; i < 64 * 64 / 4; i += 256)
        ((float4*)sW1b)[i] = ((const float4*)W1b)[i];

    int e  = t >> 2;
    int o0 = (t & 3) * 16;
    int eg = blockIdx.x * 64 + e;
    int s  = ei[eg];
    int d  = ei[E_EDGES + eg];
    float xi0 = pts[d * 3 + 0], xi1 = pts[d * 3 + 1], xi2 = pts[d * 3 + 2];
    float in6[6];
    in6[0] = xi0; in6[1] = xi1; in6[2] = xi2;
    in6[3] = pts[s * 3 + 0] - xi0;
    in6[4] = pts[s * 3 + 1] - xi1;
    in6[5] = pts[s * 3 + 2] - xi2;
    __syncthreads();

    float acc[16];
#pragma unroll
    for (int u = 0; u < 16; u++) acc[u] = __ldg(&b1a[o0 + u]);
#pragma unroll
    for (int k = 0; k < 6; k++) {
        float x = in6[k];
#pragma unroll
        for (int v = 0; v < 4; v++) {
            float4 w = *(const float4*)&sW1a[k * 64 + o0 + v * 4];
            acc[v*4+0] = fmaf(x, w.x, acc[v*4+0]);
            acc[v*4+1] = fmaf(x, w.y, acc[v*4+1]);
            acc[v*4+2] = fmaf(x, w.z, acc[v*4+2]);
            acc[v*4+3] = fmaf(x, w.w, acc[v*4+3]);
        }
    }
#pragma unroll
    for (int u = 0; u < 16; u++) sh1[e][o0 + u] = fmaxf(acc[u], 0.f);
    __syncthreads();

#pragma unroll
    for (int u = 0; u < 16; u++) acc[u] = __ldg(&b1b[o0 + u]);
#pragma unroll 8
    for (int k = 0; k < 64; k++) {
        float h = sh1[e][k];
#pragma unroll
        for (int v = 0; v < 4; v++) {
            float4 w = *(const float4*)&sW1b[k * 64 + o0 + v * 4];
            acc[v*4+0] = fmaf(h, w.x, acc[v*4+0]);
            acc[v*4+1] = fmaf(h, w.y, acc[v*4+1]);
            acc[v*4+2] = fmaf(h, w.z, acc[v*4+2]);
            acc[v*4+3] = fmaf(h, w.w, acc[v*4+3]);
        }
    }
    int base = d * FEAT + o0;
#pragma unroll
    for (int u = 0; u < 16; u++) {
        float v = fmaxf(acc[u], 0.f);   // >= 0 : int order == float order
        atomicMax((int*)(g_x1 + base + u), __float_as_int(v));
    }
}

// ---------------- squared norms (padded to 20224) ----------------------------
__global__ void k_sq() {
    int i = blockIdx.x * blockDim.x + threadIdx.x;
    if (i >= 20224) return;
    float s = 0.f;
    if (i < N_PTS) {
        const float4* r = (const float4*)(g_x1 + (size_t)i * 64);
#pragma unroll
        for (int c = 0; c < 16; c++) {
            float4 v = r[c];
            s += v.x * v.x + v.y * v.y + v.z * v.z + v.w * v.w;
        }
    }
    g_sq[i] = s;
}

// ---------------- stage 2: FFMA2 (f32x2) distance GEMM + fused top-16 -------
// 512 threads / 16 warps; block tile 128q x 128c; warp tile 32x32;
// thread tile 4q x 8c; k packed in f32x2 pairs (32 kp); cp.async dbl buffer.
#define QB      128
#define NBC     128
#define NT      ((N_PTS + NBC - 1) / NBC)   // 157
#define KP      32
#define Q_OFF   0                            // [kp][q] float2  : 32 KB
#define B_OFF   32768                        // 2 x [kp][c] float2 : 64 KB
#define SSQ_OFF (B_OFF + 65536)              // 98304 : 2 x 512 B
#define DS_OFF  (SSQ_OFF + 1024)             // 99328
#define DSR     130                          // 128 cols + 2 pad (floats)
#define KNN_SMEM (DS_OFF + 128 * DSR * 4)    // 99328 + 66560 = 165888

__device__ __forceinline__ void knn_stage_B(uint32_t sbase, int t,
                                            int tt, int buf) {
    int j0 = tt * NBC;
    int c  = t & 127;
    int g  = t >> 7;                       // 0-3
    int j  = min(j0 + c, N_PTS - 1);
    const float* src = g_x1 + (size_t)j * 64 + g * 16;
    uint32_t dst = sbase + B_OFF + buf * 32768 + c * 8;
#pragma unroll
    for (int i = 0; i < 8; i++)
        cpa8(dst + (g * 8 + i) * 1024, src + i * 2);
    if (t < 32)
        cpa16(sbase + SSQ_OFF + buf * 512 + t * 16, g_sq + j0 + t * 4);
}

__global__ void __launch_bounds__(512, 1) k_knn5() {
    extern __shared__ char smem[];
    const uint32_t sbase = smem_u32(smem);
    float* Ds = (float*)(smem + DS_OFF);

    int t    = threadIdx.x;
    int lane = t & 31;
    int w    = t >> 5;                     // 0-15
    int wq   = w & 3;                      // q slice (32 each)
    int wc   = w >> 2;                     // c slice (32 each)
    int tx   = lane & 7;                   // q pair group
    int ty   = lane >> 3;                  // c group (0-3)
    int qb   = blockIdx.x * QB;

    // ---- stage Q once: [kp][q] float2
    {
        int q = t & 127, part = t >> 7;
        int qg = min(qb + q, N_PTS - 1);
        const float4* src = (const float4*)(g_x1 + (size_t)qg * 64) + part * 4;
#pragma unroll
        for (int i = 0; i < 4; i++) {
            float4 v = src[i];
            int kp0 = part * 8 + i * 2;
            *(float2*)(smem + Q_OFF + kp0 * 1024 + q * 8) =
                make_float2(v.x, v.y);
            *(float2*)(smem + Q_OFF + (kp0 + 1) * 1024 + q * 8) =
                make_float2(v.z, v.w);
        }
    }

    knn_stage_B(sbase, t, 0, 0);
    cpa_commit();

    unsigned long long lst[16];
#pragma unroll
    for (int i = 0; i < 16; i++) lst[i] = 0xFFFFFFFFFFFFFFFFull;
    float thr = __int_as_float(0x7f800000);

    const int qbase = wq * 32 + tx * 2;    // thread queries: +{0,1,16,17}
    const int cbase = wc * 32 + ty * 2;    // thread cands:   +{0,1,8,9,16,17,24,25}

    cpa_wait0();
    __syncthreads();

    for (int tt = 0; tt < NT; tt++) {
        int buf = tt & 1;
        int j0  = tt * NBC;
        if (tt + 1 < NT) { knn_stage_B(sbase, t, tt + 1, buf ^ 1); cpa_commit(); }

        unsigned long long acc[4][8];
#pragma unroll
        for (int qi = 0; qi < 4; qi++)
#pragma unroll
            for (int ci = 0; ci < 8; ci++) acc[qi][ci] = 0ull;

        const char* qp = smem + Q_OFF + qbase * 8;
        const char* bp = smem + B_OFF + buf * 32768 + cbase * 8;
#pragma unroll 4
        for (int kp = 0; kp < KP; kp++) {
            ulonglong2 qv0 = *(const ulonglong2*)(qp);
            ulonglong2 qv1 = *(const ulonglong2*)(qp + 128);
            ulonglong2 bv0 = *(const ulonglong2*)(bp);
            ulonglong2 bv1 = *(const ulonglong2*)(bp + 64);
            ulonglong2 bv2 = *(const ulonglong2*)(bp + 128);
            ulonglong2 bv3 = *(const ulonglong2*)(bp + 192);
            unsigned long long q2[4] = {qv0.x, qv0.y, qv1.x, qv1.y};
            unsigned long long b2[8] = {bv0.x, bv0.y, bv1.x, bv1.y,
                                        bv2.x, bv2.y, bv3.x, bv3.y};
#pragma unroll
            for (int qi = 0; qi < 4; qi++)
#pragma unroll
                for (int ci = 0; ci < 8; ci++)
                    acc[qi][ci] = ffma2(q2[qi], b2[ci], acc[qi][ci]);
            qp += 1024; bp += 1024;
        }

        // ---- write dot products to Ds[q][c]
#pragma unroll
        for (int qi = 0; qi < 4; qi++) {
            int qv = qbase + (qi & 1) + (qi >> 1) * 16;
#pragma unroll
            for (int cp = 0; cp < 4; cp++) {
                float2 dv = make_float2(f32x2_sum(acc[qi][cp * 2]),
                                        f32x2_sum(acc[qi][cp * 2 + 1]));
                *(float2*)&Ds[qv * DSR + cbase + cp * 8] = dv;
            }
        }
        __syncthreads();

        // ---- scan: threads 0-255, q = t&127, half h = t>>7
        if (t < 256) {
            int q  = t & 127;
            int h  = t >> 7;
            int cb = h * 64;
            int cmax = min(128, N_PTS - j0);
            const float* ssq_s = (const float*)(smem + SSQ_OFF + buf * 512);
            for (int i = 0; i < 64; i++) {
                int c = cb + i;
                if (c >= cmax) break;
                float d = fmaf(-2.f, Ds[q * DSR + c], ssq_s[c]);
                if (d <= thr) {
                    unsigned long long key =
                        ((unsigned long long)enc_f(d) << 32)
                        | (unsigned)(j0 + c);
                    if (key < lst[15]) {
                        lst[15] = key;
#pragma unroll
                        for (int p = 15; p >= 1; p--) {
                            if (lst[p] < lst[p-1]) {
                                unsigned long long tmp = lst[p];
                                lst[p] = lst[p-1]; lst[p-1] = tmp;
                            }
                        }
                        unsigned hi = (unsigned)(lst[15] >> 32);
                        thr = (hi == 0xFFFFFFFFu)
                            ? __int_as_float(0x7f800000)
                            : ((hi & 0x80000000u)
                                   ? __uint_as_float(hi & 0x7fffffffu)
                                   : __uint_as_float(~hi));
                    }
                }
            }
        }
        cpa_wait0();
        __syncthreads();
    }

    // ---- merge half-lists (threads 128-255 -> 0-127) and store
    unsigned long long* mrg = (unsigned long long*)(smem + DS_OFF);
    if (t >= 128 && t < 256) {
        int q = t & 127;
#pragma unroll
        for (int i = 0; i < 16; i++) mrg[q * 16 + i] = lst[i];
    }
    __syncthreads();
    if (t < 128) {
        int q = t;
#pragma unroll
        for (int i = 0; i < 16; i++) {
            unsigned long long key = mrg[q * 16 + i];
            if (key >= lst[15]) break;
            lst[15] = key;
#pragma unroll
            for (int p = 15; p >= 1; p--) {
                if (lst[p] < lst[p-1]) {
                    unsigned long long tmp = lst[p];
                    lst[p] = lst[p-1]; lst[p-1] = tmp;
                }
            }
        }
        int qg = qb + q;
        if (qg < N_PTS) {
#pragma unroll
            for (int i = 0; i < 16; i++)
                g_nbr[(size_t)qg * 16 + i] = (int)(lst[i] & 0xffffffffu);
        }
    }
}

// ---------------- stage 3: pair MLP (128->64->64, ReLU) + max over K --------
__global__ void __launch_bounds__(256) k_pair(
    const float* __restrict__ W2a, const float* __restrict__ b2a,
    const float* __restrict__ W2b, const float* __restrict__ b2b)
{
    __shared__ float sT[128][66];
    __shared__ float sW[32][64];

    int t = threadIdx.x;
    int r = t >> 2, part = t & 3, o0 = part * 16;
    size_t row = (size_t)blockIdx.x * 64 + r;
    int n = (int)(row >> 4);
    int j = g_nbr[row];

    {
        const float4* xi4 = (const float4*)(g_x1 + (size_t)n * 64);
        const float4* xj4 = (const float4*)(g_x1 + (size_t)j * 64);
#pragma unroll
        for (int i = 0; i < 4; i++) {
            float4 a = xi4[part * 4 + i];
            float4 b = xj4[part * 4 + i];
            int k = (part * 4 + i) * 4;
            sT[k+0][r] = a.x;  sT[k+1][r] = a.y;  sT[k+2][r] = a.z;  sT[k+3][r] = a.w;
            sT[64+k+0][r] = b.x - a.x; sT[64+k+1][r] = b.y - a.y;
            sT[64+k+2][r] = b.z - a.z; sT[64+k+3][r] = b.w - a.w;
        }
    }

    float acc[16];
#pragma unroll
    for (int u = 0; u < 16; u++) acc[u] = __ldg(&b2a[o0 + u]);

    for (int ch = 0; ch < 4; ch++) {
        __syncthreads();
        {
            const float4* wsrc = (const float4*)(W2a) + ch * 512;
            float4* wdst = (float4*)sW;
            wdst[t] = wsrc[t];
            wdst[t + 256] = wsrc[t + 256];
        }
        __syncthreads();
#pragma unroll 8
        for (int kk = 0; kk < 32; kk++) {
            float x = sT[ch * 32 + kk][r];
#pragma unroll
            for (int v = 0; v < 4; v++) {
                float4 w = *(const float4*)&sW[kk][o0 + v * 4];
                acc[v*4+0] = fmaf(x, w.x, acc[v*4+0]);
                acc[v*4+1] = fmaf(x, w.y, acc[v*4+1]);
                acc[v*4+2] = fmaf(x, w.z, acc[v*4+2]);
                acc[v*4+3] = fmaf(x, w.w, acc[v*4+3]);
            }
        }
    }
    __syncthreads();
#pragma unroll
    for (int u = 0; u < 16; u++) sT[o0 + u][r] = fmaxf(acc[u], 0.f);

#pragma unroll
    for (int u = 0; u < 16; u++) acc[u] = __ldg(&b2b[o0 + u]);
    for (int ch = 0; ch < 2; ch++) {
        __syncthreads();
        {
            const float4* wsrc = (const float4*)(W2b) + ch * 512;
            float4* wdst = (float4*)sW;
            wdst[t] = wsrc[t];
            wdst[t + 256] = wsrc[t + 256];
        }
        __syncthreads();
#pragma unroll 8
        for (int kk = 0; kk < 32; kk++) {
            float x = sT[ch * 32 + kk][r];
#pragma unroll
            for (int v = 0; v < 4; v++) {
                float4 w = *(const float4*)&sW[kk][o0 + v * 4];
                acc[v*4+0] = fmaf(x, w.x, acc[v*4+0]);
                acc[v*4+1] = fmaf(x, w.y, acc[v*4+1]);
                acc[v*4+2] = fmaf(x, w.z, acc[v*4+2]);
                acc[v*4+3] = fmaf(x, w.w, acc[v*4+3]);
            }
        }
    }
    __syncthreads();
#pragma unroll
    for (int u = 0; u < 16; u++) sT[o0 + u][r] = fmaxf(acc[u], 0.f);
    __syncthreads();

    {
        int p = t >> 6, f = t & 63;
        float m = sT[f][p * 16];
#pragma unroll
        for (int kk = 1; kk < 16; kk++) m = fmaxf(m, sT[f][p * 16 + kk]);
        g_x2[((size_t)blockIdx.x * 4 + p) * 64 + f] = m;
    }
}

// ---------------- stage 4: fused head (We_r -> Wp -> relu(Wr1) -> Wr2) ------
__global__ void __launch_bounds__(256) k_head(
    const float* __restrict__ We,  const float* __restrict__ be,
    const float* __restrict__ Wp,  const float* __restrict__ bp,
    const float* __restrict__ Wr1, const float* __restrict__ br1,
    const float* __restrict__ Wr2, const float* __restrict__ br2,
    float* __restrict__ out)
{
    __shared__ float sT[64][66];
    __shared__ float sW[64][64];

    int t = threadIdx.x;
    int r = t >> 2, part = t & 3, o0 = part * 16;
    int rr = blockIdx.y;
    int n  = blockIdx.x * 64 + r;
    int nl = min(n, N_PTS - 1);

    {
        const float4* src = (const float4*)(g_x2 + (size_t)nl * 64);
#pragma unroll
        for (int i = 0; i < 4; i++) {
            float4 v = src[part * 4 + i];
            int k = (part * 4 + i) * 4;
            sT[k+0][r] = v.x; sT[k+1][r] = v.y; sT[k+2][r] = v.z; sT[k+3][r] = v.w;
        }
    }
    {
        int kr = t >> 2, q = t & 3;
#pragma unroll
        for (int i = 0; i < 4; i++)
            *(float4*)&sW[kr][q * 16 + i * 4] =
                *(const float4*)(We + (size_t)kr * 256 + rr * 64 + q * 16 + i * 4);
    }
    __syncthreads();

    float acc[16];
#pragma unroll
    for (int u = 0; u < 16; u++) acc[u] = __ldg(&be[rr * 64 + o0 + u]);
#pragma unroll 8
    for (int k = 0; k < 64; k++) {
        float x = sT[k][r];
#pragma unroll
        for (int v = 0; v < 4; v++) {
            float4 w = *(const float4*)&sW[k][o0 + v * 4];
            acc[v*4+0] = fmaf(x, w.x, acc[v*4+0]);
            acc[v*4+1] = fmaf(x, w.y, acc[v*4+1]);
            acc[v*4+2] = fmaf(x, w.z, acc[v*4+2]);
            acc[v*4+3] = fmaf(x, w.w, acc[v*4+3]);
        }
    }
    __syncthreads();
#pragma unroll
    for (int u = 0; u < 16; u++) sT[o0 + u][r] = acc[u];
    {
        int kr = t >> 2, q = t & 3;
#pragma unroll
        for (int i = 0; i < 4; i++)
            *(float4*)&sW[kr][q * 16 + i * 4] =
                *(const float4*)(Wp + (size_t)kr * 64 + q * 16 + i * 4);
    }
    __syncthreads();

#pragma unroll
    for (int u = 0; u < 16; u++) acc[u] = __ldg(&bp[o0 + u]);
#pragma unroll 8
    for (int k = 0; k < 64; k++) {
        float x = sT[k][r];
#pragma unroll
        for (int v = 0; v < 4; v++) {
            float4 w = *(const float4*)&sW[k][o0 + v * 4];
            acc[v*4+0] = fmaf(x, w.x, acc[v*4+0]);
            acc[v*4+1] = fmaf(x, w.y, acc[v*4+1]);
            acc[v*4+2] = fmaf(x, w.z, acc[v*4+2]);
            acc[v*4+3] = fmaf(x, w.w, acc[v*4+3]);
        }
    }
    __syncthreads();
#pragma unroll
    for (int u = 0; u < 16; u++) sT[o0 + u][r] = acc[u];
    {
        int kr = t >> 2, q = t & 3;
#pragma unroll
        for (int i = 0; i < 4; i++)
            *(float4*)&sW[kr][q * 16 + i * 4] =
                *(const float4*)(Wr1 + (size_t)kr * 64 + q * 16 + i * 4);
    }
    __syncthreads();

#pragma unroll
    for (int u = 0; u < 16; u++) acc[u] = __ldg(&br1[o0 + u]);
#pragma unroll 8
    for (int k = 0; k < 64; k++) {
        float x = sT[k][r];
#pragma unroll
        for (int v = 0; v < 4; v++) {
            float4 w = *(const float4*)&sW[k][o0 + v * 4];
            acc[v*4+0] = fmaf(x, w.x, acc[v*4+0]);
            acc[v*4+1] = fmaf(x, w.y, acc[v*4+1]);
            acc[v*4+2] = fmaf(x, w.z, acc[v*4+2]);
            acc[v*4+3] = fmaf(x, w.w, acc[v*4+3]);
        }
    }
    __syncthreads();
#pragma unroll
    for (int u = 0; u < 16; u++) sT[o0 + u][r] = fmaxf(acc[u], 0.f);
    if (t < 192) ((float*)sW)[t] = Wr2[t];
    if (t >= 192 && t < 195) ((float*)sW)[t] = br2[t - 192];
    __syncthreads();

    if (part < 3 && n < N_PTS) {
        float y = ((float*)sW)[192 + part];
#pragma unroll 8
        for (int k = 0; k < 64; k++)
            y = fmaf(sT[k][r], ((float*)sW)[k * 3 + part], y);
        out[((size_t)rr * N_PTS + n) * 3 + part] = y;
    }
}

// ---------------- launch -----------------------------------------------------
extern "C" void kernel_launch(void* const* d_in, const int* in_sizes, int n_in,
                              void* d_out, int out_size) {
    const float* pts = (const float*)d_in[0];
    const float* W1a = (const float*)d_in[1];
    const float* b1a = (const float*)d_in[2];
    const float* W1b = (const float*)d_in[3];
    const float* b1b = (const float*)d_in[4];
    const float* W2a = (const float*)d_in[5];
    const float* b2a = (const float*)d_in[6];
    const float* W2b = (const float*)d_in[7];
    const float* b2b = (const float*)d_in[8];
    const float* We  = (const float*)d_in[9];
    const float* be  = (const float*)d_in[10];
    const float* Wp  = (const float*)d_in[11];
    const float* bp  = (const float*)d_in[12];
    const float* Wr1 = (const float*)d_in[13];
    const float* br1 = (const float*)d_in[14];
    const float* Wr2 = (const float*)d_in[15];
    const float* br2 = (const float*)d_in[16];
    const int*   ei  = (const int*)d_in[17];
    float* out = (float*)d_out;

    cudaFuncSetAttribute(k_knn5, cudaFuncAttributeMaxDynamicSharedMemorySize,
                         KNN_SMEM);

    k_zero_x1<<<(N_PTS * FEAT + 255) / 256, 256>>>();
    k_edge<<<E_EDGES / 64, 256>>>(pts, ei, W1a, b1a, W1b, b1b);
    k_sq<<<(20224 + 255) / 256, 256>>>();
    k_knn5<<<(N_PTS + QB - 1) / QB, 512, KNN_SMEM>>>();
    k_pair<<<(N_PTS * KNN) / 64, 256>>>(W2a, b2a, W2b, b2b);
    k_head<<<dim3((N_PTS + 63) / 64, R_REP), 256>>>(We, be, Wp, bp, Wr1, br1,
                                                    Wr2, br2, out);
}

// round 15
// speedup vs baseline: 1.0120x; 1.0120x over previous
#include <cuda_runtime.h>
#include <cuda_bf16.h>
#include <cstddef>
#include <cstdint>

#define N_PTS   20000
#define E_EDGES 320000
#define KNN     16
#define FEAT    64
#define R_REP   4

// ---------------- scratch (static device globals; allocation-free) ----------
__device__ float g_x1[(size_t)N_PTS * FEAT];   // 5.12 MB
__device__ float g_sq[20224];                  // padded with +inf past N_PTS
__device__ int   g_nbr[(size_t)N_PTS * KNN];   // 1.28 MB
__device__ float g_x2[(size_t)N_PTS * FEAT];   // 5.12 MB

// ---------------- helpers ---------------------------------------------------
__device__ __forceinline__ unsigned enc_f(float f) {
    unsigned u = __float_as_uint(f);
    return (u & 0x80000000u) ? ~u : (u | 0x80000000u);
}
__device__ __forceinline__ uint32_t smem_u32(const void* p) {
    uint32_t a;
    asm("{ .reg .u64 t; cvta.to.shared.u64 t, %1; cvt.u32.u64 %0, t; }"
        : "=r"(a) : "l"(p));
    return a;
}
__device__ __forceinline__ unsigned long long ffma2(
    unsigned long long a, unsigned long long b, unsigned long long c) {
    unsigned long long d;
    asm("fma.rn.f32x2 %0, %1, %2, %3;" : "=l"(d) : "l"(a), "l"(b), "l"(c));
    return d;
}
__device__ __forceinline__ float f32x2_sum(unsigned long long v) {
    unsigned lo, hi;
    asm("mov.b64 {%0,%1}, %2;" : "=r"(lo), "=r"(hi) : "l"(v));
    return __uint_as_float(lo) + __uint_as_float(hi);
}
__device__ __forceinline__ void cpa8(uint32_t dst, const void* src) {
    asm volatile("cp.async.ca.shared.global [%0], [%1], 8;"
        :: "r"(dst), "l"(src));
}
__device__ __forceinline__ void cpa16(uint32_t dst, const void* src) {
    asm volatile("cp.async.cg.shared.global [%0], [%1], 16;"
        :: "r"(dst), "l"(src));
}
__device__ __forceinline__ void cpa_commit() {
    asm volatile("cp.async.commit_group;");
}
__device__ __forceinline__ void cpa_wait0() {
    asm volatile("cp.async.wait_group 0;");
}

// ---------------- zero x1 ----------------------------------------------------
__global__ void k_zero_x1() {
    int i = blockIdx.x * blockDim.x + threadIdx.x;
    if (i < N_PTS * FEAT) g_x1[i] = 0.f;
}

// ---------------- stage 1: edge MLP (6->64->64, ReLU) + segment_max ---------
__global__ void __launch_bounds__(256) k_edge(
    const float* __restrict__ pts, const int* __restrict__ ei,
    const float* __restrict__ W1a, const float* __restrict__ b1a,
    const float* __restrict__ W1b, const float* __restrict__ b1b)
{
    __shared__ float sW1a[6 * 64];
    __shared__ float sW1b[64 * 64];
    __shared__ float sh1[64][66];
    int t = threadIdx.x;
    for (int i = t; i < 6 * 64 / 4; i += 256)
        ((float4*)sW1a)[i] = ((const float4*)W1a)[i];
    for (int i = t; i < 64 * 64 / 4; i += 256)
        ((float4*)sW1b)[i] = ((const float4*)W1b)[i];

    int e  = t >> 2;
    int o0 = (t & 3) * 16;
    int eg = blockIdx.x * 64 + e;
    int s  = ei[eg];
    int d  = ei[E_EDGES + eg];
    float xi0 = pts[d * 3 + 0], xi1 = pts[d * 3 + 1], xi2 = pts[d * 3 + 2];
    float in6[6];
    in6[0] = xi0; in6[1] = xi1; in6[2] = xi2;
    in6[3] = pts[s * 3 + 0] - xi0;
    in6[4] = pts[s * 3 + 1] - xi1;
    in6[5] = pts[s * 3 + 2] - xi2;
    __syncthreads();

    float acc[16];
#pragma unroll
    for (int u = 0; u < 16; u++) acc[u] = __ldg(&b1a[o0 + u]);
#pragma unroll
    for (int k = 0; k < 6; k++) {
        float x = in6[k];
#pragma unroll
        for (int v = 0; v < 4; v++) {
            float4 w = *(const float4*)&sW1a[k * 64 + o0 + v * 4];
            acc[v*4+0] = fmaf(x, w.x, acc[v*4+0]);
            acc[v*4+1] = fmaf(x, w.y, acc[v*4+1]);
            acc[v*4+2] = fmaf(x, w.z, acc[v*4+2]);
            acc[v*4+3] = fmaf(x, w.w, acc[v*4+3]);
        }
    }
#pragma unroll
    for (int u = 0; u < 16; u++) sh1[e][o0 + u] = fmaxf(acc[u], 0.f);
    __syncthreads();

#pragma unroll
    for (int u = 0; u < 16; u++) acc[u] = __ldg(&b1b[o0 + u]);
#pragma unroll 8
    for (int k = 0; k < 64; k++) {
        float h = sh1[e][k];
#pragma unroll
        for (int v = 0; v < 4; v++) {
            float4 w = *(const float4*)&sW1b[k * 64 + o0 + v * 4];
            acc[v*4+0] = fmaf(h, w.x, acc[v*4+0]);
            acc[v*4+1] = fmaf(h, w.y, acc[v*4+1]);
            acc[v*4+2] = fmaf(h, w.z, acc[v*4+2]);
            acc[v*4+3] = fmaf(h, w.w, acc[v*4+3]);
        }
    }
    int base = d * FEAT + o0;
#pragma unroll
    for (int u = 0; u < 16; u++) {
        float v = fmaxf(acc[u], 0.f);   // >= 0 : int order == float order
        atomicMax((int*)(g_x1 + base + u), __float_as_int(v));
    }
}

// ---------------- squared norms (pad = +inf so clamped dups are excluded) ----
__global__ void k_sq() {
    int i = blockIdx.x * blockDim.x + threadIdx.x;
    if (i >= 20224) return;
    float s = __int_as_float(0x7f800000);
    if (i < N_PTS) {
        const float4* r = (const float4*)(g_x1 + (size_t)i * 64);
        s = 0.f;
#pragma unroll
        for (int c = 0; c < 16; c++) {
            float4 v = r[c];
            s += v.x * v.x + v.y * v.y + v.z * v.z + v.w * v.w;
        }
    }
    g_sq[i] = s;
}

// ---------------- stage 2: FFMA2 distance GEMM + fused top-16 ---------------
// 256 threads / 8 warps; block tile 64q x 128c; warp owns q = w*8..+7 (all
// lanes share, broadcast A); lane owns c = lane*4..+3; thread tile 8q x 4c
// in f32x2 k-pairs. cp.async double-buffered B. 2 blocks/SM.
#define QB      64
#define NBC     128
#define NT      ((N_PTS + NBC - 1) / NBC)   // 157
#define KP      32
#define Q_OFF   0                            // [kp][q] float2 : 16 KB
#define BSZ     32768                        // [kp][c] float2 per buffer
#define B_OFF   16384                        // 2 buffers -> ends 81920
#define SSQ_OFF 81920                        // 2 x 512 B
#define DS_OFF  82944                        // 8 warps x 8q x 68 floats
#define DS_WST  2176                         // bytes per warp (8*68*4)
#define KNN_SMEM (DS_OFF + 8 * DS_WST)       // 100352 (98 KB)

__device__ __forceinline__ void knn_stage_B(uint32_t sbase, int t,
                                            int tt, int buf) {
    int j0 = tt * NBC;
    int c  = t & 127;
    int g  = t >> 7;                        // 0-1 -> kp halves
    int j  = min(j0 + c, N_PTS - 1);
    const float* src = g_x1 + (size_t)j * 64 + g * 32;
    uint32_t dst = sbase + B_OFF + buf * BSZ + (g * 16) * 1024 + c * 8;
#pragma unroll
    for (int i = 0; i < 16; i++)
        cpa8(dst + i * 1024, src + i * 2);
    if (t < 32)
        cpa16(sbase + SSQ_OFF + buf * 512 + t * 16, g_sq + j0 + t * 4);
}

__global__ void __launch_bounds__(256, 2) k_knn6() {
    extern __shared__ char smem[];
    const uint32_t sbase = smem_u32(smem);

    int t    = threadIdx.x;
    int lane = t & 31;
    int w    = t >> 5;                      // 0-7
    int qb   = blockIdx.x * QB;
    float* Ds = (float*)(smem + DS_OFF + w * DS_WST);   // [8][68]

    // ---- stage Q once: [kp][q] float2, kp stride 512 B
    {
        int q = t & 63, part = t >> 6;      // part 0..3
        int qg = min(qb + q, N_PTS - 1);
        const float4* src = (const float4*)(g_x1 + (size_t)qg * 64) + part * 4;
#pragma unroll
        for (int i = 0; i < 4; i++) {
            float4 v = src[i];
            int kp0 = part * 8 + i * 2;
            *(float2*)(smem + Q_OFF + kp0 * 512 + q * 8) = make_float2(v.x, v.y);
            *(float2*)(smem + Q_OFF + (kp0 + 1) * 512 + q * 8) =
                make_float2(v.z, v.w);
        }
    }

    knn_stage_B(sbase, t, 0, 0);
    cpa_commit();

    unsigned long long lst[16];
#pragma unroll
    for (int i = 0; i < 16; i++) lst[i] = 0xFFFFFFFFFFFFFFFFull;
    float thr = __int_as_float(0x7f800000);

    cpa_wait0();
    __syncthreads();

    for (int tt = 0; tt < NT; tt++) {
        int buf = tt & 1;
        int j0  = tt * NBC;
        if (tt + 1 < NT) { knn_stage_B(sbase, t, tt + 1, buf ^ 1); cpa_commit(); }

        unsigned long long acc[8][4];
#pragma unroll
        for (int qi = 0; qi < 8; qi++)
#pragma unroll
            for (int ci = 0; ci < 4; ci++) acc[qi][ci] = 0ull;

        const char* qp = smem + Q_OFF + (w * 8) * 8;            // broadcast
        const char* bp = smem + B_OFF + buf * BSZ + lane * 32;
#pragma unroll 4
        for (int kp = 0; kp < KP; kp++) {
            ulonglong2 qA = *(const ulonglong2*)(qp);
            ulonglong2 qB = *(const ulonglong2*)(qp + 16);
            ulonglong2 qC = *(const ulonglong2*)(qp + 32);
            ulonglong2 qD = *(const ulonglong2*)(qp + 48);
            ulonglong2 bA = *(const ulonglong2*)(bp);
            ulonglong2 bB = *(const ulonglong2*)(bp + 16);
#define FFROW(qi, qv) \
            acc[qi][0] = ffma2(qv, bA.x, acc[qi][0]); \
            acc[qi][1] = ffma2(qv, bA.y, acc[qi][1]); \
            acc[qi][2] = ffma2(qv, bB.x, acc[qi][2]); \
            acc[qi][3] = ffma2(qv, bB.y, acc[qi][3]);
            FFROW(0, qA.x) FFROW(1, qA.y) FFROW(2, qB.x) FFROW(3, qB.y)
            FFROW(4, qC.x) FFROW(5, qC.y) FFROW(6, qD.x) FFROW(7, qD.y)
#undef FFROW
            qp += 512; bp += 1024;
        }

        const float* ssq_s = (const float*)(smem + SSQ_OFF + buf * 512);

        // ---- two half-passes through per-warp Ds scratch (8 x 68 floats)
#pragma unroll
        for (int half = 0; half < 2; half++) {
            if ((lane >> 4) == half) {       // this thread's 4 cols in half
                int cl = (lane * 4) - half * 64;   // 0..63
#pragma unroll
                for (int qi = 0; qi < 8; qi++) {
                    float4 dv = make_float4(f32x2_sum(acc[qi][0]),
                                            f32x2_sum(acc[qi][1]),
                                            f32x2_sum(acc[qi][2]),
                                            f32x2_sum(acc[qi][3]));
                    *(float4*)&Ds[qi * 68 + cl] = dv;
                }
            }
            __syncwarp();
            {   // scan: lane -> q = lane>>2, 16 cols at (lane&3)*16
                int q  = lane >> 2;
                int c0 = (lane & 3) * 16;
#pragma unroll
                for (int i4 = 0; i4 < 4; i4++) {
                    float4 dv = *(const float4*)&Ds[q * 68 + c0 + i4 * 4];
                    float dd[4] = {dv.x, dv.y, dv.z, dv.w};
#pragma unroll
                    for (int u = 0; u < 4; u++) {
                        int cl = c0 + i4 * 4 + u;          // 0..63 in half
                        float d = fmaf(-2.f, dd[u], ssq_s[half * 64 + cl]);
                        if (d <= thr) {
                            unsigned long long key =
                                ((unsigned long long)enc_f(d) << 32)
                                | (unsigned)(j0 + half * 64 + cl);
                            if (key < lst[15]) {
                                lst[15] = key;
#pragma unroll
                                for (int p = 15; p >= 1; p--) {
                                    if (lst[p] < lst[p-1]) {
                                        unsigned long long tmp = lst[p];
                                        lst[p] = lst[p-1]; lst[p-1] = tmp;
                                    }
                                }
                                unsigned hi = (unsigned)(lst[15] >> 32);
                                thr = (hi == 0xFFFFFFFFu)
                                    ? __int_as_float(0x7f800000)
                                    : ((hi & 0x80000000u)
                                           ? __uint_as_float(hi & 0x7fffffffu)
                                           : __uint_as_float(~hi));
                            }
                        }
                    }
                }
            }
            __syncwarp();
        }

        cpa_wait0();
        __syncthreads();
    }

    // ---- merge: 4 lists per q (lanes 4q..4q+3) -> lane 4q, store
    __syncthreads();
    unsigned long long* mrg =
        (unsigned long long*)(smem + B_OFF + w * 3072);
    int qi = lane >> 2, sub = lane & 3;
    if (sub != 0) {
#pragma unroll
        for (int i = 0; i < 16; i++)
            mrg[(qi * 3 + sub - 1) * 16 + i] = lst[i];
    }
    __syncwarp();
    if (sub == 0) {
#pragma unroll
        for (int s = 0; s < 3; s++) {
#pragma unroll
            for (int i = 0; i < 16; i++) {
                unsigned long long key = mrg[(qi * 3 + s) * 16 + i];
                if (key >= lst[15]) break;
                lst[15] = key;
#pragma unroll
                for (int p = 15; p >= 1; p--) {
                    if (lst[p] < lst[p-1]) {
                        unsigned long long tmp = lst[p];
                        lst[p] = lst[p-1]; lst[p-1] = tmp;
                    }
                }
            }
        }
        int qg = qb + w * 8 + qi;
        if (qg < N_PTS) {
#pragma unroll
            for (int i = 0; i < 16; i++)
                g_nbr[(size_t)qg * 16 + i] = (int)(lst[i] & 0xffffffffu);
        }
    }
}

// ---------------- stage 3: pair MLP (128->64->64, ReLU) + max over K --------
__global__ void __launch_bounds__(256) k_pair(
    const float* __restrict__ W2a, const float* __restrict__ b2a,
    const float* __restrict__ W2b, const float* __restrict__ b2b)
{
    __shared__ float sT[128][66];
    __shared__ float sW[32][64];

    int t = threadIdx.x;
    int r = t >> 2, part = t & 3, o0 = part * 16;
    size_t row = (size_t)blockIdx.x * 64 + r;
    int n = (int)(row >> 4);
    int j = g_nbr[row];

    {
        const float4* xi4 = (const float4*)(g_x1 + (size_t)n * 64);
        const float4* xj4 = (const float4*)(g_x1 + (size_t)j * 64);
#pragma unroll
        for (int i = 0; i < 4; i++) {
            float4 a = xi4[part * 4 + i];
            float4 b = xj4[part * 4 + i];
            int k = (part * 4 + i) * 4;
            sT[k+0][r] = a.x;  sT[k+1][r] = a.y;  sT[k+2][r] = a.z;  sT[k+3][r] = a.w;
            sT[64+k+0][r] = b.x - a.x; sT[64+k+1][r] = b.y - a.y;
            sT[64+k+2][r] = b.z - a.z; sT[64+k+3][r] = b.w - a.w;
        }
    }

    float acc[16];
#pragma unroll
    for (int u = 0; u < 16; u++) acc[u] = __ldg(&b2a[o0 + u]);

    for (int ch = 0; ch < 4; ch++) {
        __syncthreads();
        {
            const float4* wsrc = (const float4*)(W2a) + ch * 512;
            float4* wdst = (float4*)sW;
            wdst[t] = wsrc[t];
            wdst[t + 256] = wsrc[t + 256];
        }
        __syncthreads();
#pragma unroll 8
        for (int kk = 0; kk < 32; kk++) {
            float x = sT[ch * 32 + kk][r];
#pragma unroll
            for (int v = 0; v < 4; v++) {
                float4 w = *(const float4*)&sW[kk][o0 + v * 4];
                acc[v*4+0] = fmaf(x, w.x, acc[v*4+0]);
                acc[v*4+1] = fmaf(x, w.y, acc[v*4+1]);
                acc[v*4+2] = fmaf(x, w.z, acc[v*4+2]);
                acc[v*4+3] = fmaf(x, w.w, acc[v*4+3]);
            }
        }
    }
    __syncthreads();
#pragma unroll
    for (int u = 0; u < 16; u++) sT[o0 + u][r] = fmaxf(acc[u], 0.f);

#pragma unroll
    for (int u = 0; u < 16; u++) acc[u] = __ldg(&b2b[o0 + u]);
    for (int ch = 0; ch < 2; ch++) {
        __syncthreads();
        {
            const float4* wsrc = (const float4*)(W2b) + ch * 512;
            float4* wdst = (float4*)sW;
            wdst[t] = wsrc[t];
            wdst[t + 256] = wsrc[t + 256];
        }
        __syncthreads();
#pragma unroll 8
        for (int kk = 0; kk < 32; kk++) {
            float x = sT[ch * 32 + kk][r];
#pragma unroll
            for (int v = 0; v < 4; v++) {
                float4 w = *(const float4*)&sW[kk][o0 + v * 4];
                acc[v*4+0] = fmaf(x, w.x, acc[v*4+0]);
                acc[v*4+1] = fmaf(x, w.y, acc[v*4+1]);
                acc[v*4+2] = fmaf(x, w.z, acc[v*4+2]);
                acc[v*4+3] = fmaf(x, w.w, acc[v*4+3]);
            }
        }
    }
    __syncthreads();
#pragma unroll
    for (int u = 0; u < 16; u++) sT[o0 + u][r] = fmaxf(acc[u], 0.f);
    __syncthreads();

    {
        int p = t >> 6, f = t & 63;
        float m = sT[f][p * 16];
#pragma unroll
        for (int kk = 1; kk < 16; kk++) m = fmaxf(m, sT[f][p * 16 + kk]);
        g_x2[((size_t)blockIdx.x * 4 + p) * 64 + f] = m;
    }
}

// ---------------- stage 4: fused head (We_r -> Wp -> relu(Wr1) -> Wr2) ------
__global__ void __launch_bounds__(256) k_head(
    const float* __restrict__ We,  const float* __restrict__ be,
    const float* __restrict__ Wp,  const float* __restrict__ bp,
    const float* __restrict__ Wr1, const float* __restrict__ br1,
    const float* __restrict__ Wr2, const float* __restrict__ br2,
    float* __restrict__ out)
{
    __shared__ float sT[64][66];
    __shared__ float sW[64][64];

    int t = threadIdx.x;
    int r = t >> 2, part = t & 3, o0 = part * 16;
    int rr = blockIdx.y;
    int n  = blockIdx.x * 64 + r;
    int nl = min(n, N_PTS - 1);

    {
        const float4* src = (const float4*)(g_x2 + (size_t)nl * 64);
#pragma unroll
        for (int i = 0; i < 4; i++) {
            float4 v = src[part * 4 + i];
            int k = (part * 4 + i) * 4;
            sT[k+0][r] = v.x; sT[k+1][r] = v.y; sT[k+2][r] = v.z; sT[k+3][r] = v.w;
        }
    }
    {
        int kr = t >> 2, q = t & 3;
#pragma unroll
        for (int i = 0; i < 4; i++)
            *(float4*)&sW[kr][q * 16 + i * 4] =
                *(const float4*)(We + (size_t)kr * 256 + rr * 64 + q * 16 + i * 4);
    }
    __syncthreads();

    float acc[16];
#pragma unroll
    for (int u = 0; u < 16; u++) acc[u] = __ldg(&be[rr * 64 + o0 + u]);
#pragma unroll 8
    for (int k = 0; k < 64; k++) {
        float x = sT[k][r];
#pragma unroll
        for (int v = 0; v < 4; v++) {
            float4 w = *(const float4*)&sW[k][o0 + v * 4];
            acc[v*4+0] = fmaf(x, w.x, acc[v*4+0]);
            acc[v*4+1] = fmaf(x, w.y, acc[v*4+1]);
            acc[v*4+2] = fmaf(x, w.z, acc[v*4+2]);
            acc[v*4+3] = fmaf(x, w.w, acc[v*4+3]);
        }
    }
    __syncthreads();
#pragma unroll
    for (int u = 0; u < 16; u++) sT[o0 + u][r] = acc[u];
    {
        int kr = t >> 2, q = t & 3;
#pragma unroll
        for (int i = 0; i < 4; i++)
            *(float4*)&sW[kr][q * 16 + i * 4] =
                *(const float4*)(Wp + (size_t)kr * 64 + q * 16 + i * 4);
    }
    __syncthreads();

#pragma unroll
    for (int u = 0; u < 16; u++) acc[u] = __ldg(&bp[o0 + u]);
#pragma unroll 8
    for (int k = 0; k < 64; k++) {
        float x = sT[k][r];
#pragma unroll
        for (int v = 0; v < 4; v++) {
            float4 w = *(const float4*)&sW[k][o0 + v * 4];
            acc[v*4+0] = fmaf(x, w.x, acc[v*4+0]);
            acc[v*4+1] = fmaf(x, w.y, acc[v*4+1]);
            acc[v*4+2] = fmaf(x, w.z, acc[v*4+2]);
            acc[v*4+3] = fmaf(x, w.w, acc[v*4+3]);
        }
    }
    __syncthreads();
#pragma unroll
    for (int u = 0; u < 16; u++) sT[o0 + u][r] = acc[u];
    {
        int kr = t >> 2, q = t & 3;
#pragma unroll
        for (int i = 0; i < 4; i++)
            *(float4*)&sW[kr][q * 16 + i * 4] =
                *(const float4*)(Wr1 + (size_t)kr * 64 + q * 16 + i * 4);
    }
    __syncthreads();

#pragma unroll
    for (int u = 0; u < 16; u++) acc[u] = __ldg(&br1[o0 + u]);
#pragma unroll 8
    for (int k = 0; k < 64; k++) {
        float x = sT[k][r];
#pragma unroll
        for (int v = 0; v < 4; v++) {
            float4 w = *(const float4*)&sW[k][o0 + v * 4];
            acc[v*4+0] = fmaf(x, w.x, acc[v*4+0]);
            acc[v*4+1] = fmaf(x, w.y, acc[v*4+1]);
            acc[v*4+2] = fmaf(x, w.z, acc[v*4+2]);
            acc[v*4+3] = fmaf(x, w.w, acc[v*4+3]);
        }
    }
    __syncthreads();
#pragma unroll
    for (int u = 0; u < 16; u++) sT[o0 + u][r] = fmaxf(acc[u], 0.f);
    if (t < 192) ((float*)sW)[t] = Wr2[t];
    if (t >= 192 && t < 195) ((float*)sW)[t] = br2[t - 192];
    __syncthreads();

    if (part < 3 && n < N_PTS) {
        float y = ((float*)sW)[192 + part];
#pragma unroll 8
        for (int k = 0; k < 64; k++)
            y = fmaf(sT[k][r], ((float*)sW)[k * 3 + part], y);
        out[((size_t)rr * N_PTS + n) * 3 + part] = y;
    }
}

// ---------------- launch -----------------------------------------------------
extern "C" void kernel_launch(void* const* d_in, const int* in_sizes, int n_in,
                              void* d_out, int out_size) {
    const float* pts = (const float*)d_in[0];
    const float* W1a = (const float*)d_in[1];
    const float* b1a = (const float*)d_in[2];
    const float* W1b = (const float*)d_in[3];
    const float* b1b = (const float*)d_in[4];
    const float* W2a = (const float*)d_in[5];
    const float* b2a = (const float*)d_in[6];
    const float* W2b = (const float*)d_in[7];
    const float* b2b = (const float*)d_in[8];
    const float* We  = (const float*)d_in[9];
    const float* be  = (const float*)d_in[10];
    const float* Wp  = (const float*)d_in[11];
    const float* bp  = (const float*)d_in[12];
    const float* Wr1 = (const float*)d_in[13];
    const float* br1 = (const float*)d_in[14];
    const float* Wr2 = (const float*)d_in[15];
    const float* br2 = (const float*)d_in[16];
    const int*   ei  = (const int*)d_in[17];
    float* out = (float*)d_out;

    cudaFuncSetAttribute(k_knn6, cudaFuncAttributeMaxDynamicSharedMemorySize,
                         KNN_SMEM);

    k_zero_x1<<<(N_PTS * FEAT + 255) / 256, 256>>>();
    k_edge<<<E_EDGES / 64, 256>>>(pts, ei, W1a, b1a, W1b, b1b);
    k_sq<<<(20224 + 255) / 256, 256>>>();
    k_knn6<<<(N_PTS + QB - 1) / QB, 256, KNN_SMEM>>>();
    k_pair<<<(N_PTS * KNN) / 64, 256>>>(W2a, b2a, W2b, b2b);
    k_head<<<dim3((N_PTS + 63) / 64, R_REP), 256>>>(We, be, Wp, bp, Wr1, br1,
                                                    Wr2, br2, out);
}